// round 15
// baseline (speedup 1.0000x reference)
#include <cuda_runtime.h>
#include <cuda_fp16.h>

// Scratch (__device__ globals; zero-init at load). N = 100000 <= MAXN.
// Rotated zeroing (R8 scheme): each accumulator re-zeroed by a later kernel
// in the same call, after its consumer has read it:
//   g_deg : atomics in deg_kernel -> read by prep  -> zeroed in scatter<0>
//   g_S   : atomics in scatter<0> -> read by t     -> zeroed in scatter<1>
//   g_acc : atomics in scatter<1> -> read by final -> zeroed in deg_kernel
#define MAXN (1 << 17)
__device__ __align__(16) float  g_deg[MAXN];
__device__ __align__(16) float  g_dinv[MAXN];
__device__ __align__(16) __half g_a[MAXN];    // dinv[i]*x[i]  (fp16, 200KB: L1-resident)
__device__ __align__(16) float  g_S[MAXN];    // layer-1 aggregate (fp32 REDs)
__device__ __align__(16) __half g_u[MAXN];    // dinv[i]*t[i]  (fp16)
__device__ __align__(16) float  g_acc[MAXN];  // layer-2 aggregate

#define EPT  8   // edges/thread in deg_kernel
#define SEPT 8   // edges/thread in scatter kernels (was 4)

// ---------------------------------------------------------------------------
// Node kernels
// ---------------------------------------------------------------------------

__global__ void prep_kernel(const float* __restrict__ x, int n) {
    int i4 = (blockIdx.x * blockDim.x + threadIdx.x) * 4;
    if (i4 + 3 < n) {
        float4 xv = *reinterpret_cast<const float4*>(x + i4);
        float4 dv = *reinterpret_cast<const float4*>(g_deg + i4);
        float4 di;
        di.x = 1.0f / sqrtf(dv.x + 1.0f);
        di.y = 1.0f / sqrtf(dv.y + 1.0f);
        di.z = 1.0f / sqrtf(dv.z + 1.0f);
        di.w = 1.0f / sqrtf(dv.w + 1.0f);
        *reinterpret_cast<float4*>(g_dinv + i4) = di;
        *reinterpret_cast<__half2*>(g_a + i4)     = __floats2half2_rn(di.x * xv.x, di.y * xv.y);
        *reinterpret_cast<__half2*>(g_a + i4 + 2) = __floats2half2_rn(di.z * xv.z, di.w * xv.w);
    } else {
        for (int i = i4; i < n; i++) {
            float di = 1.0f / sqrtf(g_deg[i] + 1.0f);
            g_dinv[i] = di;
            g_a[i] = __float2half_rn(di * x[i]);
        }
    }
}

__global__ void t_kernel(const float* __restrict__ W1,
                         const float* __restrict__ b1,
                         const float* __restrict__ W2,
                         int n, int H) {
    int i = blockIdx.x * blockDim.x + threadIdx.x;
    if (i < n) {
        float di = g_dinv[i];
        float s  = di * (g_S[i] + __half2float(g_a[i]));
        float acc = 0.0f;
        #pragma unroll 16
        for (int k = 0; k < H; k++) {
            float h = fmaf(__ldg(&W1[k]), s, __ldg(&b1[k]));
            h = fmaxf(h, 0.0f);
            acc = fmaf(h, __ldg(&W2[k]), acc);
        }
        g_u[i] = __float2half_rn(di * acc);
    }
}

__global__ void final_kernel(const float* __restrict__ b2,
                             float* __restrict__ out, int n) {
    int i = blockIdx.x * blockDim.x + threadIdx.x;
    if (i < n) {
        out[i] = g_dinv[i] * (g_acc[i] + __half2float(g_u[i])) + __ldg(&b2[0]);
    }
}

// ---------------------------------------------------------------------------
// Edge kernels. Index streams use __ldcs (evict-first -> fp16 gather table
// stays L1-resident). Gathers use __ldg (allocate). Max-L1 carveout set host-side.
// ---------------------------------------------------------------------------

// deg[col] += 1 (REDG floor). Also zeroes g_acc.
__global__ void __launch_bounds__(256, 8)
deg_kernel(const int* __restrict__ col, int E, int N) {
    int i = blockIdx.x * blockDim.x + threadIdx.x;
    if (i < N) g_acc[i] = 0.0f;

    int e = i * EPT;
    if (e + EPT - 1 < E) {
        int idx[EPT];
        #pragma unroll
        for (int v = 0; v < EPT / 4; v++) {
            int4 c = __ldcs(reinterpret_cast<const int4*>(col + e + v * 4));
            idx[v * 4 + 0] = c.x; idx[v * 4 + 1] = c.y;
            idx[v * 4 + 2] = c.z; idx[v * 4 + 3] = c.w;
        }
        #pragma unroll
        for (int v = 0; v < EPT; v++) atomicAdd(&g_deg[idx[v]], 1.0f);
    } else {
        for (; e < E; e++) atomicAdd(&g_deg[col[e]], 1.0f);
    }
}

// Scatter pass: dst[col] += table[row].
// PASS=0: g_a -> g_S (zeroes g_deg).  PASS=1: g_u -> g_acc (zeroes g_S).
template <int PASS>
__global__ void __launch_bounds__(256, 8)
scatter_kernel(const int* __restrict__ row, const int* __restrict__ col,
               int E, int N) {
    const __half* table = (PASS == 0) ? g_a : g_u;
    float* dst          = (PASS == 0) ? g_S : g_acc;

    int i = blockIdx.x * blockDim.x + threadIdx.x;

    // fused zeroing of the already-consumed accumulator
    if (i < N) {
        if (PASS == 0) g_deg[i] = 0.0f;
        else           g_S[i]   = 0.0f;
    }

    int e = i * SEPT;
    if (e + SEPT - 1 < E) {
        int rs[SEPT], cs[SEPT];
        #pragma unroll
        for (int v = 0; v < SEPT / 4; v++) {
            int4 r = __ldcs(reinterpret_cast<const int4*>(row + e + v * 4));
            int4 c = __ldcs(reinterpret_cast<const int4*>(col + e + v * 4));
            rs[v * 4 + 0] = r.x; rs[v * 4 + 1] = r.y;
            rs[v * 4 + 2] = r.z; rs[v * 4 + 3] = r.w;
            cs[v * 4 + 0] = c.x; cs[v * 4 + 1] = c.y;
            cs[v * 4 + 2] = c.z; cs[v * 4 + 3] = c.w;
        }
        float vals[SEPT];
        #pragma unroll
        for (int v = 0; v < SEPT; v++) vals[v] = __half2float(__ldg(table + rs[v]));
        #pragma unroll
        for (int v = 0; v < SEPT; v++) atomicAdd(&dst[cs[v]], vals[v]);
    } else {
        for (; e < E; e++)
            atomicAdd(&dst[col[e]], __half2float(__ldg(table + row[e])));
    }
}

// ---------------------------------------------------------------------------
// Launch
// ---------------------------------------------------------------------------

extern "C" void kernel_launch(void* const* d_in, const int* in_sizes, int n_in,
                              void* d_out, int out_size) {
    const float* x    = (const float*)d_in[0];
    const int*   eidx = (const int*)d_in[1];    // [2, E] int32
    const float* W1   = (const float*)d_in[2];
    const float* b1   = (const float*)d_in[3];
    const float* W2   = (const float*)d_in[4];
    const float* b2   = (const float*)d_in[5];
    float*       out  = (float*)d_out;

    int N = in_sizes[0];
    int E = in_sizes[1] / 2;
    int H = in_sizes[3];

    const int* row = eidx;
    const int* col = eidx + E;

    // Max-L1 carveout for the table-gathering kernels (no smem used).
    // Idempotent host-side attribute -> capture-safe, no allocation.
    cudaFuncSetAttribute(scatter_kernel<0>,
                         cudaFuncAttributePreferredSharedMemoryCarveout, 0);
    cudaFuncSetAttribute(scatter_kernel<1>,
                         cudaFuncAttributePreferredSharedMemoryCarveout, 0);
    cudaFuncSetAttribute(deg_kernel,
                         cudaFuncAttributePreferredSharedMemoryCarveout, 0);

    const int TB = 256;
    int nodeBlocks  = (N + TB - 1) / TB;
    int node4Blocks = ((N + 3) / 4 + TB - 1) / TB;
    int degThreads  = (E + EPT - 1) / EPT;
    int degBlocks   = (max(degThreads, N) + TB - 1) / TB;
    int scatThreads = (E + SEPT - 1) / SEPT;
    int scatBlocks  = (max(scatThreads, N) + TB - 1) / TB;

    deg_kernel<<<degBlocks, TB>>>(col, E, N);
    prep_kernel<<<node4Blocks, TB>>>(x, N);
    scatter_kernel<0><<<scatBlocks, TB>>>(row, col, E, N);
    t_kernel<<<nodeBlocks, TB>>>(W1, b1, W2, N, H);
    scatter_kernel<1><<<scatBlocks, TB>>>(row, col, E, N);
    final_kernel<<<nodeBlocks, TB>>>(b2, out, N);
}

// round 16
// speedup vs baseline: 1.0153x; 1.0153x over previous
#include <cuda_runtime.h>
#include <cuda_fp16.h>

// Scratch (__device__ globals; zero-init at load). N = 100000 <= MAXN.
// Rotated zeroing (R8 scheme): each accumulator re-zeroed by a later kernel
// in the same call, after its consumer has read it:
//   g_deg : atomics in deg_kernel -> read by prep  -> zeroed in scatter<0>
//   g_S   : atomics in scatter<0> -> read by t     -> zeroed in scatter<1>
//   g_acc : atomics in scatter<1> -> read by final -> zeroed in deg_kernel
#define MAXN (1 << 17)
__device__ __align__(16) float  g_deg[MAXN];
__device__ __align__(16) float  g_dinv[MAXN];
__device__ __align__(16) __half g_a[MAXN];    // dinv[i]*x[i]  (fp16, 200KB: L1-resident)
__device__ __align__(16) float  g_S[MAXN];    // layer-1 aggregate (fp32 REDs)
__device__ __align__(16) __half g_u[MAXN];    // dinv[i]*t[i]  (fp16)
__device__ __align__(16) float  g_acc[MAXN];  // layer-2 aggregate

#define EPT  8   // edges/thread in deg_kernel
#define SEPT 4   // edges/thread in scatter kernels (R14 sweet spot)

// ---------------------------------------------------------------------------
// Node kernels
// ---------------------------------------------------------------------------

__global__ void prep_kernel(const float* __restrict__ x, int n) {
    int i4 = (blockIdx.x * blockDim.x + threadIdx.x) * 4;
    if (i4 + 3 < n) {
        float4 xv = __ldcs(reinterpret_cast<const float4*>(x + i4));
        float4 dv = *reinterpret_cast<const float4*>(g_deg + i4);
        float4 di;
        di.x = 1.0f / sqrtf(dv.x + 1.0f);
        di.y = 1.0f / sqrtf(dv.y + 1.0f);
        di.z = 1.0f / sqrtf(dv.z + 1.0f);
        di.w = 1.0f / sqrtf(dv.w + 1.0f);
        *reinterpret_cast<float4*>(g_dinv + i4) = di;
        *reinterpret_cast<__half2*>(g_a + i4)     = __floats2half2_rn(di.x * xv.x, di.y * xv.y);
        *reinterpret_cast<__half2*>(g_a + i4 + 2) = __floats2half2_rn(di.z * xv.z, di.w * xv.w);
    } else {
        for (int i = i4; i < n; i++) {
            float di = 1.0f / sqrtf(g_deg[i] + 1.0f);
            g_dinv[i] = di;
            g_a[i] = __float2half_rn(di * x[i]);
        }
    }
}

// 2 nodes/thread with interleaved MLPs (doubles ILP in the FMA chain).
__global__ void t_kernel(const float* __restrict__ W1,
                         const float* __restrict__ b1,
                         const float* __restrict__ W2,
                         int n, int H) {
    int i2 = (blockIdx.x * blockDim.x + threadIdx.x) * 2;
    if (i2 + 1 < n) {
        float di0 = g_dinv[i2],     di1 = g_dinv[i2 + 1];
        __half2 a01 = *reinterpret_cast<const __half2*>(g_a + i2);
        float2 av = __half22float2(a01);
        float s0 = di0 * (g_S[i2]     + av.x);
        float s1 = di1 * (g_S[i2 + 1] + av.y);
        float acc0 = 0.0f, acc1 = 0.0f;
        #pragma unroll 16
        for (int k = 0; k < H; k++) {
            float w = __ldg(&W1[k]), b = __ldg(&b1[k]), w2 = __ldg(&W2[k]);
            float h0 = fmaxf(fmaf(w, s0, b), 0.0f);
            float h1 = fmaxf(fmaf(w, s1, b), 0.0f);
            acc0 = fmaf(h0, w2, acc0);
            acc1 = fmaf(h1, w2, acc1);
        }
        *reinterpret_cast<__half2*>(g_u + i2) =
            __floats2half2_rn(di0 * acc0, di1 * acc1);
    } else if (i2 < n) {
        int i = i2;
        float di = g_dinv[i];
        float s  = di * (g_S[i] + __half2float(g_a[i]));
        float acc = 0.0f;
        for (int k = 0; k < H; k++) {
            float h = fmaxf(fmaf(__ldg(&W1[k]), s, __ldg(&b1[k])), 0.0f);
            acc = fmaf(h, __ldg(&W2[k]), acc);
        }
        g_u[i] = __float2half_rn(di * acc);
    }
}

__global__ void final_kernel(const float* __restrict__ b2,
                             float* __restrict__ out, int n) {
    int i = blockIdx.x * blockDim.x + threadIdx.x;
    if (i < n) {
        out[i] = g_dinv[i] * (g_acc[i] + __half2float(g_u[i])) + __ldg(&b2[0]);
    }
}

// ---------------------------------------------------------------------------
// Edge kernels. Index streams use __ldcs (evict-first -> fp16 gather table
// stays L1-resident). Gathers use __ldg. Max-L1 carveout set host-side.
// ---------------------------------------------------------------------------

// deg[col] += 1 (REDG floor). Also zeroes g_acc.
__global__ void __launch_bounds__(256, 8)
deg_kernel(const int* __restrict__ col, int E, int N) {
    int i = blockIdx.x * blockDim.x + threadIdx.x;
    if (i < N) g_acc[i] = 0.0f;

    int e = i * EPT;
    if (e + EPT - 1 < E) {
        int idx[EPT];
        #pragma unroll
        for (int v = 0; v < EPT / 4; v++) {
            int4 c = __ldcs(reinterpret_cast<const int4*>(col + e + v * 4));
            idx[v * 4 + 0] = c.x; idx[v * 4 + 1] = c.y;
            idx[v * 4 + 2] = c.z; idx[v * 4 + 3] = c.w;
        }
        #pragma unroll
        for (int v = 0; v < EPT; v++) atomicAdd(&g_deg[idx[v]], 1.0f);
    } else {
        for (; e < E; e++) atomicAdd(&g_deg[col[e]], 1.0f);
    }
}

// Scatter pass: dst[col] += table[row].
// PASS=0: g_a -> g_S (zeroes g_deg).  PASS=1: g_u -> g_acc (zeroes g_S).
template <int PASS>
__global__ void __launch_bounds__(256, 8)
scatter_kernel(const int* __restrict__ row, const int* __restrict__ col,
               int E, int N) {
    const __half* table = (PASS == 0) ? g_a : g_u;
    float* dst          = (PASS == 0) ? g_S : g_acc;

    int i = blockIdx.x * blockDim.x + threadIdx.x;

    // fused zeroing of the already-consumed accumulator
    if (i < N) {
        if (PASS == 0) g_deg[i] = 0.0f;
        else           g_S[i]   = 0.0f;
    }

    int e = i * SEPT;
    if (e + SEPT - 1 < E) {
        int4 r = __ldcs(reinterpret_cast<const int4*>(row + e));
        int4 c = __ldcs(reinterpret_cast<const int4*>(col + e));
        float v0 = __half2float(__ldg(table + r.x));
        float v1 = __half2float(__ldg(table + r.y));
        float v2 = __half2float(__ldg(table + r.z));
        float v3 = __half2float(__ldg(table + r.w));
        atomicAdd(&dst[c.x], v0);
        atomicAdd(&dst[c.y], v1);
        atomicAdd(&dst[c.z], v2);
        atomicAdd(&dst[c.w], v3);
    } else {
        for (; e < E; e++)
            atomicAdd(&dst[col[e]], __half2float(__ldg(table + row[e])));
    }
}

// ---------------------------------------------------------------------------
// Launch
// ---------------------------------------------------------------------------

extern "C" void kernel_launch(void* const* d_in, const int* in_sizes, int n_in,
                              void* d_out, int out_size) {
    const float* x    = (const float*)d_in[0];
    const int*   eidx = (const int*)d_in[1];    // [2, E] int32
    const float* W1   = (const float*)d_in[2];
    const float* b1   = (const float*)d_in[3];
    const float* W2   = (const float*)d_in[4];
    const float* b2   = (const float*)d_in[5];
    float*       out  = (float*)d_out;

    int N = in_sizes[0];
    int E = in_sizes[1] / 2;
    int H = in_sizes[3];

    const int* row = eidx;
    const int* col = eidx + E;

    // Max-L1 carveout for the gather-heavy kernels (no smem used).
    // Idempotent host-side attribute -> capture-safe, no allocation.
    cudaFuncSetAttribute(scatter_kernel<0>,
                         cudaFuncAttributePreferredSharedMemoryCarveout, 0);
    cudaFuncSetAttribute(scatter_kernel<1>,
                         cudaFuncAttributePreferredSharedMemoryCarveout, 0);
    cudaFuncSetAttribute(deg_kernel,
                         cudaFuncAttributePreferredSharedMemoryCarveout, 0);

    const int TB = 256;
    int nodeBlocks  = (N + TB - 1) / TB;
    int node2Blocks = ((N + 1) / 2 + TB - 1) / TB;
    int node4Blocks = ((N + 3) / 4 + TB - 1) / TB;
    int degThreads  = (E + EPT - 1) / EPT;
    int degBlocks   = (max(degThreads, N) + TB - 1) / TB;
    int scatThreads = (E + SEPT - 1) / SEPT;
    int scatBlocks  = (max(scatThreads, N) + TB - 1) / TB;

    deg_kernel<<<degBlocks, TB>>>(col, E, N);
    prep_kernel<<<node4Blocks, TB>>>(x, N);
    scatter_kernel<0><<<scatBlocks, TB>>>(row, col, E, N);
    t_kernel<<<node2Blocks, TB>>>(W1, b1, W2, N, H);
    scatter_kernel<1><<<scatBlocks, TB>>>(row, col, E, N);
    final_kernel<<<nodeBlocks, TB>>>(b2, out, N);
}

// round 17
// speedup vs baseline: 1.0155x; 1.0002x over previous
#include <cuda_runtime.h>
#include <cuda_fp16.h>

// Scratch (__device__ globals; zero-init at load). N = 100000 <= MAXN.
// Rotated zeroing — pure STG in node kernels, never in edge kernels:
//   g_acc : REDs in scatter<1> -> read by final -> zeroed by NEXT call's prep
//   g_deg : REDs in deg_kernel -> read by prep  -> zeroed by t_kernel
//   g_S   : REDs in scatter<0> -> read by t     -> zeroed by final_kernel
// First call correct via static zero-init; invariant restored every call.
#define MAXN (1 << 17)
__device__ __align__(16) float  g_deg[MAXN];
__device__ __align__(16) float  g_dinv[MAXN];
__device__ __align__(16) __half g_a[MAXN];    // dinv[i]*x[i]  (fp16, 200KB: L1-resident)
__device__ __align__(16) float  g_S[MAXN];    // layer-1 aggregate (fp32 REDs)
__device__ __align__(16) __half g_u[MAXN];    // dinv[i]*t[i]  (fp16)
__device__ __align__(16) float  g_acc[MAXN];  // layer-2 aggregate

#define EPT  8   // edges/thread in deg_kernel
#define SEPT 4   // edges/thread in scatter kernels (confirmed sweet spot)

// ---------------------------------------------------------------------------
// Node kernels
// ---------------------------------------------------------------------------

// dinv = 1/sqrt(deg+1); a = dinv*x (fp16). Also zeroes g_acc (pure STG;
// consumed by last call's final; next writer scatter<1> runs later this call).
__global__ void prep_kernel(const float* __restrict__ x, int n) {
    int i4 = (blockIdx.x * blockDim.x + threadIdx.x) * 4;
    if (i4 + 3 < n) {
        float4 xv = __ldcs(reinterpret_cast<const float4*>(x + i4));
        float4 dv = *reinterpret_cast<const float4*>(g_deg + i4);
        *reinterpret_cast<float4*>(g_acc + i4) = make_float4(0.f, 0.f, 0.f, 0.f);
        float4 di;
        di.x = 1.0f / sqrtf(dv.x + 1.0f);
        di.y = 1.0f / sqrtf(dv.y + 1.0f);
        di.z = 1.0f / sqrtf(dv.z + 1.0f);
        di.w = 1.0f / sqrtf(dv.w + 1.0f);
        *reinterpret_cast<float4*>(g_dinv + i4) = di;
        *reinterpret_cast<__half2*>(g_a + i4)     = __floats2half2_rn(di.x * xv.x, di.y * xv.y);
        *reinterpret_cast<__half2*>(g_a + i4 + 2) = __floats2half2_rn(di.z * xv.z, di.w * xv.w);
    } else {
        for (int i = i4; i < n; i++) {
            float di = 1.0f / sqrtf(g_deg[i] + 1.0f);
            g_acc[i] = 0.0f;
            g_dinv[i] = di;
            g_a[i] = __float2half_rn(di * x[i]);
        }
    }
}

// s = dinv*(S+a); t = MLP(s); u = dinv*t (fp16). Also zeroes g_deg (pure STG;
// g_deg is dead after prep consumed it).
__global__ void t_kernel(const float* __restrict__ W1,
                         const float* __restrict__ b1,
                         const float* __restrict__ W2,
                         int n, int H) {
    int i = blockIdx.x * blockDim.x + threadIdx.x;
    if (i < n) {
        g_deg[i] = 0.0f;
        float di = g_dinv[i];
        float s  = di * (g_S[i] + __half2float(g_a[i]));
        float acc = 0.0f;
        #pragma unroll 16
        for (int k = 0; k < H; k++) {
            float h = fmaf(__ldg(&W1[k]), s, __ldg(&b1[k]));
            h = fmaxf(h, 0.0f);
            acc = fmaf(h, __ldg(&W2[k]), acc);
        }
        g_u[i] = __float2half_rn(di * acc);
    }
}

// out = dinv*(acc + u) + b2. Also zeroes g_S (pure STG; dead after t_kernel).
__global__ void final_kernel(const float* __restrict__ b2,
                             float* __restrict__ out, int n) {
    int i = blockIdx.x * blockDim.x + threadIdx.x;
    if (i < n) {
        g_S[i] = 0.0f;
        out[i] = g_dinv[i] * (g_acc[i] + __half2float(g_u[i])) + __ldg(&b2[0]);
    }
}

// ---------------------------------------------------------------------------
// Edge kernels — PURE edge work. Index streams use __ldcs (evict-first so the
// fp16 gather table stays L1-resident); gathers use __ldg. Max-L1 carveout.
// ---------------------------------------------------------------------------

// deg[col] += 1 (REDG floor).
__global__ void __launch_bounds__(256, 8)
deg_kernel(const int* __restrict__ col, int E) {
    int i = blockIdx.x * blockDim.x + threadIdx.x;
    int e = i * EPT;
    if (e + EPT - 1 < E) {
        int idx[EPT];
        #pragma unroll
        for (int v = 0; v < EPT / 4; v++) {
            int4 c = __ldcs(reinterpret_cast<const int4*>(col + e + v * 4));
            idx[v * 4 + 0] = c.x; idx[v * 4 + 1] = c.y;
            idx[v * 4 + 2] = c.z; idx[v * 4 + 3] = c.w;
        }
        #pragma unroll
        for (int v = 0; v < EPT; v++) atomicAdd(&g_deg[idx[v]], 1.0f);
    } else {
        for (; e < E; e++) atomicAdd(&g_deg[col[e]], 1.0f);
    }
}

// Scatter pass: dst[col] += table[row].
// PASS=0: g_a -> g_S.  PASS=1: g_u -> g_acc.
template <int PASS>
__global__ void __launch_bounds__(256, 8)
scatter_kernel(const int* __restrict__ row, const int* __restrict__ col, int E) {
    const __half* table = (PASS == 0) ? g_a : g_u;
    float* dst          = (PASS == 0) ? g_S : g_acc;

    int i = blockIdx.x * blockDim.x + threadIdx.x;
    int e = i * SEPT;
    if (e + SEPT - 1 < E) {
        int4 r = __ldcs(reinterpret_cast<const int4*>(row + e));
        int4 c = __ldcs(reinterpret_cast<const int4*>(col + e));
        float v0 = __half2float(__ldg(table + r.x));
        float v1 = __half2float(__ldg(table + r.y));
        float v2 = __half2float(__ldg(table + r.z));
        float v3 = __half2float(__ldg(table + r.w));
        atomicAdd(&dst[c.x], v0);
        atomicAdd(&dst[c.y], v1);
        atomicAdd(&dst[c.z], v2);
        atomicAdd(&dst[c.w], v3);
    } else {
        for (; e < E; e++)
            atomicAdd(&dst[col[e]], __half2float(__ldg(table + row[e])));
    }
}

// ---------------------------------------------------------------------------
// Launch
// ---------------------------------------------------------------------------

extern "C" void kernel_launch(void* const* d_in, const int* in_sizes, int n_in,
                              void* d_out, int out_size) {
    const float* x    = (const float*)d_in[0];
    const int*   eidx = (const int*)d_in[1];    // [2, E] int32
    const float* W1   = (const float*)d_in[2];
    const float* b1   = (const float*)d_in[3];
    const float* W2   = (const float*)d_in[4];
    const float* b2   = (const float*)d_in[5];
    float*       out  = (float*)d_out;

    int N = in_sizes[0];
    int E = in_sizes[1] / 2;
    int H = in_sizes[3];

    const int* row = eidx;
    const int* col = eidx + E;

    // Max-L1 carveout for the gather-heavy kernels (no smem used).
    // Idempotent host-side attribute -> capture-safe, no allocation.
    cudaFuncSetAttribute(scatter_kernel<0>,
                         cudaFuncAttributePreferredSharedMemoryCarveout, 0);
    cudaFuncSetAttribute(scatter_kernel<1>,
                         cudaFuncAttributePreferredSharedMemoryCarveout, 0);
    cudaFuncSetAttribute(deg_kernel,
                         cudaFuncAttributePreferredSharedMemoryCarveout, 0);

    const int TB = 256;
    int nodeBlocks  = (N + TB - 1) / TB;
    int node4Blocks = ((N + 3) / 4 + TB - 1) / TB;
    int degBlocks   = ((E + EPT - 1) / EPT + TB - 1) / TB;
    int scatBlocks  = ((E + SEPT - 1) / SEPT + TB - 1) / TB;

    deg_kernel<<<degBlocks, TB>>>(col, E);
    prep_kernel<<<node4Blocks, TB>>>(x, N);
    scatter_kernel<0><<<scatBlocks, TB>>>(row, col, E);
    t_kernel<<<nodeBlocks, TB>>>(W1, b1, W2, N, H);
    scatter_kernel<1><<<scatBlocks, TB>>>(row, col, E);
    final_kernel<<<nodeBlocks, TB>>>(b2, out, N);
}